// round 8
// baseline (speedup 1.0000x reference)
#include <cuda_runtime.h>

// moving_image [1,1,192,192,192] f32, vector_field [1,3,192,192,192] f32,
// fixed_image [1,1,192,192,192] f32, fixed_image_mask (uint8/int32/float32, runtime-detected).
// Output scalar f32 = sum((warp(mov,vf)-fixed)^2 * mask) / max(sum(mask),1).

#define DD 192
#define HH 192
#define WW 192
#define NVOX (DD * HH * WW)

#define THREADS 256                       // 8 warps; 1 warp = 1 row
#define ROWS_PER_BLK 8
#define NBLK ((DD * HH) / ROWS_PER_BLK)   // 4608
#define XITER (WW / 32)                   // 6 voxels per lane, x = lane + 32*j

__device__ float g_part_sq[NBLK];
__device__ float g_part_m[NBLK];
__device__ unsigned int g_done = 0;       // reset by last block each run -> replay-safe

__device__ __forceinline__ float sample_zero_pad(const float* __restrict__ mov,
                                                 int iz, int iy, int ix) {
    if ((unsigned)iz >= DD || (unsigned)iy >= HH || (unsigned)ix >= WW) return 0.0f;
    return __ldg(mov + (iz * HH + iy) * WW + ix);
}

__device__ __forceinline__ float trilerp(const float* __restrict__ mov,
                                         float zz, float yy, float xx) {
    int z0 = __float2int_rd(zz);
    int y0 = __float2int_rd(yy);
    int x0 = __float2int_rd(xx);
    float wz = zz - (float)z0;
    float wy = yy - (float)y0;
    float wx = xx - (float)x0;

    if ((unsigned)z0 <= DD - 2 && (unsigned)y0 <= HH - 2 && (unsigned)x0 <= WW - 2) {
        // Interior fast path: 8 direct gathers (keep default L1-caching: mov has reuse).
        const float* p = mov + ((z0 * HH + y0) * WW + x0);
        float c000 = __ldg(p);
        float c001 = __ldg(p + 1);
        float c010 = __ldg(p + WW);
        float c011 = __ldg(p + WW + 1);
        const float* q = p + HH * WW;
        float c100 = __ldg(q);
        float c101 = __ldg(q + 1);
        float c110 = __ldg(q + WW);
        float c111 = __ldg(q + WW + 1);
        float l00 = fmaf(wx, c001 - c000, c000);
        float l01 = fmaf(wx, c011 - c010, c010);
        float l10 = fmaf(wx, c101 - c100, c100);
        float l11 = fmaf(wx, c111 - c110, c110);
        float lz0 = fmaf(wy, l01 - l00, l00);
        float lz1 = fmaf(wy, l11 - l10, l10);
        return fmaf(wz, lz1 - lz0, lz0);
    } else {
        float wz0 = 1.0f - wz, wy0 = 1.0f - wy, wx0 = 1.0f - wx;
        int z1 = z0 + 1, y1 = y0 + 1, x1 = x0 + 1;
        float c000 = sample_zero_pad(mov, z0, y0, x0);
        float c001 = sample_zero_pad(mov, z0, y0, x1);
        float c010 = sample_zero_pad(mov, z0, y1, x0);
        float c011 = sample_zero_pad(mov, z0, y1, x1);
        float c100 = sample_zero_pad(mov, z1, y0, x0);
        float c101 = sample_zero_pad(mov, z1, y0, x1);
        float c110 = sample_zero_pad(mov, z1, y1, x0);
        float c111 = sample_zero_pad(mov, z1, y1, x1);
        return wz0 * (wy0 * (wx0 * c000 + wx * c001) +
                      wy  * (wx0 * c010 + wx * c011)) +
               wz  * (wy0 * (wx0 * c100 + wx * c101) +
                      wy  * (wx0 * c110 + wx * c111));
    }
}

__global__ __launch_bounds__(THREADS, 8) void warp_mse_kernel(
    const float* __restrict__ mov,
    const float* __restrict__ vf,
    const float* __restrict__ fix,
    const void* __restrict__ mask_raw,
    float* __restrict__ out) {

    __shared__ int sh_mode;
    __shared__ bool sh_last;

    const int tid = threadIdx.x;
    const int lane = tid & 31;
    const int wid = tid >> 5;

    // Per-block mask encoding detection from the first 256 bytes (L1/L2-resident).
    if (wid == 0) {
        const unsigned char* mb = (const unsigned char*)mask_raw;
        int f32 = 0, mis = 0;
#pragma unroll
        for (int k = 0; k < 8; k++) {
            int pos = lane * 8 + k;
            unsigned char b = __ldg(mb + pos);
            int off = pos & 3;
            if (off == 3 && b == 0x3f) f32 = 1;
            if (off == 2 && b == 0x80) f32 = 1;
            if (off != 0 && b != 0) mis = 1;
        }
        unsigned f32b = __ballot_sync(0xffffffffu, f32);
        unsigned misb = __ballot_sync(0xffffffffu, mis);
        if (lane == 0) sh_mode = f32b ? 2 : (misb ? 0 : 1);
    }
    __syncthreads();
    const int mask_mode = sh_mode;

    const int row = blockIdx.x * ROWS_PER_BLK + wid;
    const int y = row % HH;
    const int z = row / HH;
    const int rowbase = row * WW;
    const float zf = (float)z;
    const float yf = (float)y;

    float s_sq = 0.0f;
    float s_m = 0.0f;

#pragma unroll
    for (int j = 0; j < XITER; j++) {
        const int x = lane + 32 * j;
        const int idx = rowbase + x;

        // Streaming (zero-reuse) loads: evict-first so mov keeps L1.
        float dz = __ldcs(vf + idx);
        float dy = __ldcs(vf + idx + NVOX);
        float dx = __ldcs(vf + idx + 2 * NVOX);
        float fv = __ldcs(fix + idx);

        float m;
        if (mask_mode == 1) {
            m = (float)__ldcs((const int*)mask_raw + idx);
        } else if (mask_mode == 2) {
            m = __ldcs((const float*)mask_raw + idx);
        } else {
            m = (float)__ldcs((const unsigned char*)mask_raw + idx);
        }

        float warped = trilerp(mov, zf + dz, yf + dy, (float)x + dx);
        float d = warped - fv;
        s_sq = fmaf(d * d, m, s_sq);
        s_m += m;
    }

    // Deterministic block tree reduction.
    __shared__ float sh_sq[THREADS];
    __shared__ float sh_m[THREADS];
    sh_sq[tid] = s_sq;
    sh_m[tid] = s_m;
    __syncthreads();
    for (int off = THREADS / 2; off > 0; off >>= 1) {
        if (tid < off) {
            sh_sq[tid] += sh_sq[tid + off];
            sh_m[tid] += sh_m[tid + off];
        }
        __syncthreads();
    }
    if (tid == 0) {
        g_part_sq[blockIdx.x] = sh_sq[0];
        g_part_m[blockIdx.x] = sh_m[0];
        __threadfence();
        unsigned int t = atomicAdd(&g_done, 1u);
        sh_last = (t == (unsigned)(NBLK - 1));
    }
    __syncthreads();

    // Last block reduces all partials (fixed index order -> deterministic).
    if (sh_last) {
        float t_sq = 0.0f, t_m = 0.0f;
        for (int i = tid; i < NBLK; i += THREADS) {
            t_sq += g_part_sq[i];
            t_m += g_part_m[i];
        }
        sh_sq[tid] = t_sq;
        sh_m[tid] = t_m;
        __syncthreads();
        for (int off = THREADS / 2; off > 0; off >>= 1) {
            if (tid < off) {
                sh_sq[tid] += sh_sq[tid + off];
                sh_m[tid] += sh_m[tid + off];
            }
            __syncthreads();
        }
        if (tid == 0) {
            out[0] = sh_sq[0] / fmaxf(sh_m[0], 1.0f);
            g_done = 0;  // reset for next graph replay
        }
    }
}

extern "C" void kernel_launch(void* const* d_in, const int* in_sizes, int n_in,
                              void* d_out, int out_size) {
    const float* mov = (const float*)d_in[0];
    const float* vf = (const float*)d_in[1];
    const float* fix = (const float*)d_in[2];
    const void* mask = d_in[3];
    float* out = (float*)d_out;

    warp_mse_kernel<<<NBLK, THREADS>>>(mov, vf, fix, mask, out);
}

// round 9
// speedup vs baseline: 1.0557x; 1.0557x over previous
#include <cuda_runtime.h>

// moving_image [1,1,192,192,192] f32, vector_field [1,3,192,192,192] f32,
// fixed_image [1,1,192,192,192] f32, fixed_image_mask (uint8/int32/float32, runtime-detected).
// Output scalar f32 = sum((warp(mov,vf)-fixed)^2 * mask) / max(sum(mask),1).

#define DD 192
#define HH 192
#define WW 192
#define NVOX (DD * HH * WW)

#define THREADS 256                       // 8 warps; 1 warp = 1 row
#define ROWS_PER_BLK 8
#define NBLK ((DD * HH) / ROWS_PER_BLK)   // 4608
#define XITER (WW / 32)                   // 6 voxels per lane, x = lane + 32*j

__device__ float g_part_sq[NBLK];
__device__ float g_part_m[NBLK];
__device__ unsigned int g_done = 0;       // reset by last block each run -> replay-safe

__device__ __forceinline__ float sample_zero_pad(const float* __restrict__ mov,
                                                 int iz, int iy, int ix) {
    if ((unsigned)iz >= DD || (unsigned)iy >= HH || (unsigned)ix >= WW) return 0.0f;
    return __ldg(mov + (iz * HH + iy) * WW + ix);
}

__device__ __forceinline__ float trilerp(const float* __restrict__ mov,
                                         float zz, float yy, float xx) {
    int z0 = __float2int_rd(zz);
    int y0 = __float2int_rd(yy);
    int x0 = __float2int_rd(xx);
    float wz = zz - (float)z0;
    float wy = yy - (float)y0;
    float wx = xx - (float)x0;
    float wz0 = 1.0f - wz, wy0 = 1.0f - wy, wx0 = 1.0f - wx;

    if ((unsigned)z0 <= DD - 2 && (unsigned)y0 <= HH - 2 && (unsigned)x0 <= WW - 2) {
        // Interior fast path: 8 direct gathers.
        const float* p = mov + ((z0 * HH + y0) * WW + x0);
        float c000 = __ldg(p);
        float c001 = __ldg(p + 1);
        float c010 = __ldg(p + WW);
        float c011 = __ldg(p + WW + 1);
        const float* q = p + HH * WW;
        float c100 = __ldg(q);
        float c101 = __ldg(q + 1);
        float c110 = __ldg(q + WW);
        float c111 = __ldg(q + WW + 1);
        return wz0 * (wy0 * (wx0 * c000 + wx * c001) +
                      wy  * (wx0 * c010 + wx * c011)) +
               wz  * (wy0 * (wx0 * c100 + wx * c101) +
                      wy  * (wx0 * c110 + wx * c111));
    } else {
        int z1 = z0 + 1, y1 = y0 + 1, x1 = x0 + 1;
        float c000 = sample_zero_pad(mov, z0, y0, x0);
        float c001 = sample_zero_pad(mov, z0, y0, x1);
        float c010 = sample_zero_pad(mov, z0, y1, x0);
        float c011 = sample_zero_pad(mov, z0, y1, x1);
        float c100 = sample_zero_pad(mov, z1, y0, x0);
        float c101 = sample_zero_pad(mov, z1, y0, x1);
        float c110 = sample_zero_pad(mov, z1, y1, x0);
        float c111 = sample_zero_pad(mov, z1, y1, x1);
        return wz0 * (wy0 * (wx0 * c000 + wx * c001) +
                      wy  * (wx0 * c010 + wx * c011)) +
               wz  * (wy0 * (wx0 * c100 + wx * c101) +
                      wy  * (wx0 * c110 + wx * c111));
    }
}

__global__ __launch_bounds__(THREADS) void warp_mse_kernel(
    const float* __restrict__ mov,
    const float* __restrict__ vf,
    const float* __restrict__ fix,
    const void* __restrict__ mask_raw,
    float* __restrict__ out) {

    __shared__ int sh_mode;
    __shared__ bool sh_last;

    const int tid = threadIdx.x;
    const int lane = tid & 31;
    const int wid = tid >> 5;

    // Per-block mask encoding detection from the first 256 bytes (L1/L2-resident).
    if (wid == 0) {
        const unsigned char* mb = (const unsigned char*)mask_raw;
        int f32 = 0, mis = 0;
#pragma unroll
        for (int k = 0; k < 8; k++) {
            int pos = lane * 8 + k;
            unsigned char b = __ldg(mb + pos);
            int off = pos & 3;
            if (off == 3 && b == 0x3f) f32 = 1;
            if (off == 2 && b == 0x80) f32 = 1;
            if (off != 0 && b != 0) mis = 1;
        }
        unsigned f32b = __ballot_sync(0xffffffffu, f32);
        unsigned misb = __ballot_sync(0xffffffffu, mis);
        if (lane == 0) sh_mode = f32b ? 2 : (misb ? 0 : 1);
    }
    __syncthreads();
    const int mask_mode = sh_mode;

    const int row = blockIdx.x * ROWS_PER_BLK + wid;
    const int y = row % HH;
    const int z = row / HH;
    const int rowbase = row * WW;
    const float zf = (float)z;
    const float yf = (float)y;

    float s_sq = 0.0f;
    float s_m = 0.0f;

#pragma unroll
    for (int j = 0; j < XITER; j++) {
        const int x = lane + 32 * j;
        const int idx = rowbase + x;

        float dz = __ldg(vf + idx);
        float dy = __ldg(vf + idx + NVOX);
        float dx = __ldg(vf + idx + 2 * NVOX);
        float fv = __ldg(fix + idx);

        float m;
        if (mask_mode == 1) {
            m = (float)__ldg((const int*)mask_raw + idx);
        } else if (mask_mode == 2) {
            m = __ldg((const float*)mask_raw + idx);
        } else {
            m = (float)__ldg((const unsigned char*)mask_raw + idx);
        }

        float warped = trilerp(mov, zf + dz, yf + dy, (float)x + dx);
        float d = warped - fv;
        s_sq = fmaf(d * d, m, s_sq);
        s_m += m;
    }

    // Deterministic block tree reduction.
    __shared__ float sh_sq[THREADS];
    __shared__ float sh_m[THREADS];
    sh_sq[tid] = s_sq;
    sh_m[tid] = s_m;
    __syncthreads();
    for (int off = THREADS / 2; off > 0; off >>= 1) {
        if (tid < off) {
            sh_sq[tid] += sh_sq[tid + off];
            sh_m[tid] += sh_m[tid + off];
        }
        __syncthreads();
    }
    if (tid == 0) {
        g_part_sq[blockIdx.x] = sh_sq[0];
        g_part_m[blockIdx.x] = sh_m[0];
        __threadfence();
        unsigned int t = atomicAdd(&g_done, 1u);
        sh_last = (t == (unsigned)(NBLK - 1));
    }
    __syncthreads();

    // Last block reduces all partials (fixed index order -> deterministic).
    if (sh_last) {
        float t_sq = 0.0f, t_m = 0.0f;
        for (int i = tid; i < NBLK; i += THREADS) {
            t_sq += g_part_sq[i];
            t_m += g_part_m[i];
        }
        sh_sq[tid] = t_sq;
        sh_m[tid] = t_m;
        __syncthreads();
        for (int off = THREADS / 2; off > 0; off >>= 1) {
            if (tid < off) {
                sh_sq[tid] += sh_sq[tid + off];
                sh_m[tid] += sh_m[tid + off];
            }
            __syncthreads();
        }
        if (tid == 0) {
            out[0] = sh_sq[0] / fmaxf(sh_m[0], 1.0f);
            g_done = 0;  // reset for next graph replay
        }
    }
}

extern "C" void kernel_launch(void* const* d_in, const int* in_sizes, int n_in,
                              void* d_out, int out_size) {
    const float* mov = (const float*)d_in[0];
    const float* vf = (const float*)d_in[1];
    const float* fix = (const float*)d_in[2];
    const void* mask = d_in[3];
    float* out = (float*)d_out;

    warp_mse_kernel<<<NBLK, THREADS>>>(mov, vf, fix, mask, out);
}

// round 10
// speedup vs baseline: 1.1485x; 1.0880x over previous
#include <cuda_runtime.h>

// moving_image [1,1,192,192,192] f32, vector_field [1,3,192,192,192] f32,
// fixed_image [1,1,192,192,192] f32, fixed_image_mask (uint8/int32/float32, runtime-detected).
// Output scalar f32 = sum((warp(mov,vf)-fixed)^2 * mask) / max(sum(mask),1).

#define DD 192
#define HH 192
#define WW 192
#define NVOX (DD * HH * WW)

#define THREADS 256                       // 8 warps; 1 warp = 1 row
#define ROWS_PER_BLK 8
#define NBLK ((DD * HH) / ROWS_PER_BLK)   // 4608
#define PITER 3                           // 3 iters, each lane does an x-pair: x = 2*lane + 64*j

__device__ float g_part_sq[NBLK];
__device__ float g_part_m[NBLK];

__device__ __forceinline__ float sample_zero_pad(const float* __restrict__ mov,
                                                 int iz, int iy, int ix) {
    if ((unsigned)iz >= DD || (unsigned)iy >= HH || (unsigned)ix >= WW) return 0.0f;
    return __ldg(mov + (iz * HH + iy) * WW + ix);
}

__device__ __forceinline__ float trilerp(const float* __restrict__ mov,
                                         float zz, float yy, float xx) {
    int z0 = __float2int_rd(zz);
    int y0 = __float2int_rd(yy);
    int x0 = __float2int_rd(xx);
    float wz = zz - (float)z0;
    float wy = yy - (float)y0;
    float wx = xx - (float)x0;
    float wz0 = 1.0f - wz, wy0 = 1.0f - wy, wx0 = 1.0f - wx;

    if ((unsigned)z0 <= DD - 2 && (unsigned)y0 <= HH - 2 && (unsigned)x0 <= WW - 2) {
        // Interior fast path: 8 direct scalar gathers (proven optimal form).
        const float* p = mov + ((z0 * HH + y0) * WW + x0);
        float c000 = __ldg(p);
        float c001 = __ldg(p + 1);
        float c010 = __ldg(p + WW);
        float c011 = __ldg(p + WW + 1);
        const float* q = p + HH * WW;
        float c100 = __ldg(q);
        float c101 = __ldg(q + 1);
        float c110 = __ldg(q + WW);
        float c111 = __ldg(q + WW + 1);
        return wz0 * (wy0 * (wx0 * c000 + wx * c001) +
                      wy  * (wx0 * c010 + wx * c011)) +
               wz  * (wy0 * (wx0 * c100 + wx * c101) +
                      wy  * (wx0 * c110 + wx * c111));
    } else {
        int z1 = z0 + 1, y1 = y0 + 1, x1 = x0 + 1;
        float c000 = sample_zero_pad(mov, z0, y0, x0);
        float c001 = sample_zero_pad(mov, z0, y0, x1);
        float c010 = sample_zero_pad(mov, z0, y1, x0);
        float c011 = sample_zero_pad(mov, z0, y1, x1);
        float c100 = sample_zero_pad(mov, z1, y0, x0);
        float c101 = sample_zero_pad(mov, z1, y0, x1);
        float c110 = sample_zero_pad(mov, z1, y1, x0);
        float c111 = sample_zero_pad(mov, z1, y1, x1);
        return wz0 * (wy0 * (wx0 * c000 + wx * c001) +
                      wy  * (wx0 * c010 + wx * c011)) +
               wz  * (wy0 * (wx0 * c100 + wx * c101) +
                      wy  * (wx0 * c110 + wx * c111));
    }
}

__global__ __launch_bounds__(THREADS) void warp_mse_kernel(
    const float* __restrict__ mov,
    const float* __restrict__ vf,
    const float* __restrict__ fix,
    const void* __restrict__ mask_raw) {

    __shared__ int sh_mode;

    const int tid = threadIdx.x;
    const int lane = tid & 31;
    const int wid = tid >> 5;

    // Per-block mask encoding detection from the first 256 bytes (L1/L2-resident).
    //  - float32 0/1: byte 0x3f at pos%4==3 or 0x80 at pos%4==2 -> mode 2
    //  - int32 0/1: all bytes at pos%4!=0 zero -> mode 1
    //  - uint8 0/1: nonzero byte at pos%4!=0 (P[miss] ~ 2^-192) -> mode 0
    if (wid == 0) {
        const unsigned char* mb = (const unsigned char*)mask_raw;
        int f32 = 0, mis = 0;
#pragma unroll
        for (int k = 0; k < 8; k++) {
            int pos = lane * 8 + k;
            unsigned char b = __ldg(mb + pos);
            int off = pos & 3;
            if (off == 3 && b == 0x3f) f32 = 1;
            if (off == 2 && b == 0x80) f32 = 1;
            if (off != 0 && b != 0) mis = 1;
        }
        unsigned f32b = __ballot_sync(0xffffffffu, f32);
        unsigned misb = __ballot_sync(0xffffffffu, mis);
        if (lane == 0) sh_mode = f32b ? 2 : (misb ? 0 : 1);
    }
    __syncthreads();
    const int mask_mode = sh_mode;

    const int row = blockIdx.x * ROWS_PER_BLK + wid;
    const int y = row % HH;
    const int z = row / HH;
    const int rowbase = row * WW;
    const float zf = (float)z;
    const float yf = (float)y;

    float s_sq = 0.0f;
    float s_m = 0.0f;

    // Each lane owns x-pairs: x = 2*lane + 64*j (8B-aligned -> 64-bit streaming loads).
#pragma unroll
    for (int j = 0; j < PITER; j++) {
        const int x = 2 * lane + 64 * j;
        const int idx = rowbase + x;

        float2 dz2 = __ldg((const float2*)(vf + idx));
        float2 dy2 = __ldg((const float2*)(vf + idx + NVOX));
        float2 dx2 = __ldg((const float2*)(vf + idx + 2 * NVOX));
        float2 f2 = __ldg((const float2*)(fix + idx));

        float mA, mB;
        if (mask_mode == 1) {
            int2 mi = __ldg((const int2*)((const int*)mask_raw + idx));
            mA = (float)mi.x; mB = (float)mi.y;
        } else if (mask_mode == 2) {
            float2 mf = __ldg((const float2*)((const float*)mask_raw + idx));
            mA = mf.x; mB = mf.y;
        } else {
            unsigned short mp = __ldg((const unsigned short*)((const unsigned char*)mask_raw + idx));
            mA = (float)(mp & 0xff); mB = (float)(mp >> 8);
        }

        float wA = trilerp(mov, zf + dz2.x, yf + dy2.x, (float)x + dx2.x);
        float wB = trilerp(mov, zf + dz2.y, yf + dy2.y, (float)(x + 1) + dx2.y);

        float dA = wA - f2.x;
        float dB = wB - f2.y;
        s_sq = fmaf(dA * dA, mA, s_sq);
        s_sq = fmaf(dB * dB, mB, s_sq);
        s_m += mA + mB;
    }

    // Deterministic block tree reduction.
    __shared__ float sh_sq[THREADS];
    __shared__ float sh_m[THREADS];
    sh_sq[tid] = s_sq;
    sh_m[tid] = s_m;
    __syncthreads();
    for (int off = THREADS / 2; off > 0; off >>= 1) {
        if (tid < off) {
            sh_sq[tid] += sh_sq[tid + off];
            sh_m[tid] += sh_m[tid + off];
        }
        __syncthreads();
    }
    if (tid == 0) {
        g_part_sq[blockIdx.x] = sh_sq[0];
        g_part_m[blockIdx.x] = sh_m[0];
    }
}

__global__ __launch_bounds__(1024) void finalize_kernel(float* __restrict__ out) {
    __shared__ float sh_sq[1024];
    __shared__ float sh_m[1024];
    int tid = threadIdx.x;
    float s_sq = 0.0f, s_m = 0.0f;
    for (int i = tid; i < NBLK; i += 1024) {
        s_sq += g_part_sq[i];
        s_m += g_part_m[i];
    }
    sh_sq[tid] = s_sq;
    sh_m[tid] = s_m;
    __syncthreads();
    for (int off = 512; off > 0; off >>= 1) {
        if (tid < off) {
            sh_sq[tid] += sh_sq[tid + off];
            sh_m[tid] += sh_m[tid + off];
        }
        __syncthreads();
    }
    if (tid == 0) {
        out[0] = sh_sq[0] / fmaxf(sh_m[0], 1.0f);
    }
}

extern "C" void kernel_launch(void* const* d_in, const int* in_sizes, int n_in,
                              void* d_out, int out_size) {
    const float* mov = (const float*)d_in[0];
    const float* vf = (const float*)d_in[1];
    const float* fix = (const float*)d_in[2];
    const void* mask = d_in[3];
    float* out = (float*)d_out;

    warp_mse_kernel<<<NBLK, THREADS>>>(mov, vf, fix, mask);
    finalize_kernel<<<1, 1024>>>(out);
}

// round 11
// speedup vs baseline: 1.6052x; 1.3976x over previous
#include <cuda_runtime.h>

// moving_image [1,1,192,192,192] f32, vector_field [1,3,192,192,192] f32,
// fixed_image [1,1,192,192,192] f32, fixed_image_mask (uint8/int32/float32, runtime-detected).
// Output scalar f32 = sum((warp(mov,vf)-fixed)^2 * mask) / max(sum(mask),1).

#define DD 192
#define HH 192
#define WW 192
#define NVOX (DD * HH * WW)

#define THREADS 256                       // 8 warps; 1 warp = 1 row
#define ROWS_PER_BLK 8
#define NBLK ((DD * HH) / ROWS_PER_BLK)   // 4608
#define PITER 3                           // 3 iters, each lane does an x-pair: x = 2*lane + 64*j

__device__ float g_part_sq[NBLK];
__device__ float g_part_m[NBLK];

__device__ __forceinline__ float sample_zero_pad(const float* __restrict__ mov,
                                                 int iz, int iy, int ix) {
    if ((unsigned)iz >= DD || (unsigned)iy >= HH || (unsigned)ix >= WW) return 0.0f;
    return __ldg(mov + (iz * HH + iy) * WW + ix);
}

__device__ __forceinline__ float trilerp(const float* __restrict__ mov,
                                         float zz, float yy, float xx) {
    int z0 = __float2int_rd(zz);
    int y0 = __float2int_rd(yy);
    int x0 = __float2int_rd(xx);
    float wz = zz - (float)z0;
    float wy = yy - (float)y0;
    float wx = xx - (float)x0;
    float wz0 = 1.0f - wz, wy0 = 1.0f - wy, wx0 = 1.0f - wx;

    if ((unsigned)z0 <= DD - 2 && (unsigned)y0 <= HH - 2 && (unsigned)x0 <= WW - 2) {
        // Interior fast path: 8 direct scalar gathers (proven optimal form).
        const float* p = mov + ((z0 * HH + y0) * WW + x0);
        float c000 = __ldg(p);
        float c001 = __ldg(p + 1);
        float c010 = __ldg(p + WW);
        float c011 = __ldg(p + WW + 1);
        const float* q = p + HH * WW;
        float c100 = __ldg(q);
        float c101 = __ldg(q + 1);
        float c110 = __ldg(q + WW);
        float c111 = __ldg(q + WW + 1);
        return wz0 * (wy0 * (wx0 * c000 + wx * c001) +
                      wy  * (wx0 * c010 + wx * c011)) +
               wz  * (wy0 * (wx0 * c100 + wx * c101) +
                      wy  * (wx0 * c110 + wx * c111));
    } else {
        int z1 = z0 + 1, y1 = y0 + 1, x1 = x0 + 1;
        float c000 = sample_zero_pad(mov, z0, y0, x0);
        float c001 = sample_zero_pad(mov, z0, y0, x1);
        float c010 = sample_zero_pad(mov, z0, y1, x0);
        float c011 = sample_zero_pad(mov, z0, y1, x1);
        float c100 = sample_zero_pad(mov, z1, y0, x0);
        float c101 = sample_zero_pad(mov, z1, y0, x1);
        float c110 = sample_zero_pad(mov, z1, y1, x0);
        float c111 = sample_zero_pad(mov, z1, y1, x1);
        return wz0 * (wy0 * (wx0 * c000 + wx * c001) +
                      wy  * (wx0 * c010 + wx * c011)) +
               wz  * (wy0 * (wx0 * c100 + wx * c101) +
                      wy  * (wx0 * c110 + wx * c111));
    }
}

__global__ __launch_bounds__(THREADS) void warp_mse_kernel(
    const float* __restrict__ mov,
    const float* __restrict__ vf,
    const float* __restrict__ fix,
    const void* __restrict__ mask_raw) {

    __shared__ int sh_mode;

    const int tid = threadIdx.x;
    const int lane = tid & 31;
    const int wid = tid >> 5;

    // Per-block mask encoding detection from the first 256 bytes (L1/L2-resident).
    //  - float32 0/1: byte 0x3f at pos%4==3 or 0x80 at pos%4==2 -> mode 2
    //  - int32 0/1: all bytes at pos%4!=0 zero -> mode 1
    //  - uint8 0/1: nonzero byte at pos%4!=0 (P[miss] ~ 2^-192) -> mode 0
    if (wid == 0) {
        const unsigned char* mb = (const unsigned char*)mask_raw;
        int f32 = 0, mis = 0;
#pragma unroll
        for (int k = 0; k < 8; k++) {
            int pos = lane * 8 + k;
            unsigned char b = __ldg(mb + pos);
            int off = pos & 3;
            if (off == 3 && b == 0x3f) f32 = 1;
            if (off == 2 && b == 0x80) f32 = 1;
            if (off != 0 && b != 0) mis = 1;
        }
        unsigned f32b = __ballot_sync(0xffffffffu, f32);
        unsigned misb = __ballot_sync(0xffffffffu, mis);
        if (lane == 0) sh_mode = f32b ? 2 : (misb ? 0 : 1);
    }
    __syncthreads();
    const int mask_mode = sh_mode;

    const int row = blockIdx.x * ROWS_PER_BLK + wid;
    const int y = row % HH;
    const int z = row / HH;
    const int rowbase = row * WW;
    const float zf = (float)z;
    const float yf = (float)y;

    float s_sq = 0.0f;
    float s_m = 0.0f;

    // Each lane owns x-pairs: x = 2*lane + 64*j (8B-aligned -> 64-bit streaming loads).
#pragma unroll
    for (int j = 0; j < PITER; j++) {
        const int x = 2 * lane + 64 * j;
        const int idx = rowbase + x;

        float2 dz2 = __ldg((const float2*)(vf + idx));
        float2 dy2 = __ldg((const float2*)(vf + idx + NVOX));
        float2 dx2 = __ldg((const float2*)(vf + idx + 2 * NVOX));
        float2 f2 = __ldg((const float2*)(fix + idx));

        float mA, mB;
        if (mask_mode == 1) {
            int2 mi = __ldg((const int2*)((const int*)mask_raw + idx));
            mA = (float)mi.x; mB = (float)mi.y;
        } else if (mask_mode == 2) {
            float2 mf = __ldg((const float2*)((const float*)mask_raw + idx));
            mA = mf.x; mB = mf.y;
        } else {
            unsigned short mp = __ldg((const unsigned short*)((const unsigned char*)mask_raw + idx));
            mA = (float)(mp & 0xff); mB = (float)(mp >> 8);
        }

        // Masked-out voxels contribute exactly 0 -> skip their 8 gathers entirely.
        // Predicated-off lanes issue no memory requests -> fewer L1tex wavefronts.
        if (mA != 0.0f) {
            float wA = trilerp(mov, zf + dz2.x, yf + dy2.x, (float)x + dx2.x);
            float dA = wA - f2.x;
            s_sq = fmaf(dA * dA, mA, s_sq);
        }
        if (mB != 0.0f) {
            float wB = trilerp(mov, zf + dz2.y, yf + dy2.y, (float)(x + 1) + dx2.y);
            float dB = wB - f2.y;
            s_sq = fmaf(dB * dB, mB, s_sq);
        }
        s_m += mA + mB;
    }

    // Deterministic block tree reduction.
    __shared__ float sh_sq[THREADS];
    __shared__ float sh_m[THREADS];
    sh_sq[tid] = s_sq;
    sh_m[tid] = s_m;
    __syncthreads();
    for (int off = THREADS / 2; off > 0; off >>= 1) {
        if (tid < off) {
            sh_sq[tid] += sh_sq[tid + off];
            sh_m[tid] += sh_m[tid + off];
        }
        __syncthreads();
    }
    if (tid == 0) {
        g_part_sq[blockIdx.x] = sh_sq[0];
        g_part_m[blockIdx.x] = sh_m[0];
    }
}

__global__ __launch_bounds__(1024) void finalize_kernel(float* __restrict__ out) {
    __shared__ float sh_sq[1024];
    __shared__ float sh_m[1024];
    int tid = threadIdx.x;
    float s_sq = 0.0f, s_m = 0.0f;
    for (int i = tid; i < NBLK; i += 1024) {
        s_sq += g_part_sq[i];
        s_m += g_part_m[i];
    }
    sh_sq[tid] = s_sq;
    sh_m[tid] = s_m;
    __syncthreads();
    for (int off = 512; off > 0; off >>= 1) {
        if (tid < off) {
            sh_sq[tid] += sh_sq[tid + off];
            sh_m[tid] += sh_m[tid + off];
        }
        __syncthreads();
    }
    if (tid == 0) {
        out[0] = sh_sq[0] / fmaxf(sh_m[0], 1.0f);
    }
}

extern "C" void kernel_launch(void* const* d_in, const int* in_sizes, int n_in,
                              void* d_out, int out_size) {
    const float* mov = (const float*)d_in[0];
    const float* vf = (const float*)d_in[1];
    const float* fix = (const float*)d_in[2];
    const void* mask = d_in[3];
    float* out = (float*)d_out;

    warp_mse_kernel<<<NBLK, THREADS>>>(mov, vf, fix, mask);
    finalize_kernel<<<1, 1024>>>(out);
}